// round 6
// baseline (speedup 1.0000x reference)
#include <cuda_runtime.h>
#include <math.h>

#define IN_C   64
#define OUT_C  64
#define NUM_RELS 32
#define N_NODES 20000
#define N_EDGES 50000
#define CHUNKS 7
#define EDGE_BLOCKS ((N_EDGES + 255) / 256)     // 196

// ---------------- device scratch ----------------
// one contiguous zeroed region: [0,2N) degrees | hist 32 | cursor 32 | ticket
#define PREP_INTS (2 * N_NODES + NUM_RELS + NUM_RELS + 1)
__device__ __align__(16) int g_prep[PREP_INTS];
#define G_DEG_SRC  (g_prep)
#define G_DEG_DST  (g_prep + N_NODES)
#define G_HIST     (g_prep + 2 * N_NODES)
#define G_CURSOR   (g_prep + 2 * N_NODES + NUM_RELS)
#define G_TICKET   (g_prep + 2 * N_NODES + 2 * NUM_RELS)

__device__ int   g_off[NUM_RELS + 1];
__device__ float g_wscale[2 * NUM_RELS];   // 1/(||W||+0.01) per (dir,type)
__device__ int   g_esrc[N_EDGES];
__device__ int   g_edst[N_EDGES];

// ---- packed f32x2 helpers ----
__device__ __forceinline__ void fma2(unsigned long long& d,
                                     unsigned long long a, unsigned long long b) {
    asm("fma.rn.f32x2 %0, %1, %2, %0;" : "+l"(d) : "l"(a), "l"(b));
}
__device__ __forceinline__ unsigned long long pack2(float v) {
    unsigned long long r;
    asm("mov.b64 %0, {%1, %1};" : "=l"(r) : "f"(v));
    return r;
}
__device__ __forceinline__ void unpack2(unsigned long long v, float& lo, float& hi) {
    asm("mov.b64 {%0, %1}, %2;" : "=f"(lo), "=f"(hi) : "l"(v));
}
__device__ __forceinline__ unsigned long long d_as_ull(double d) {
    return __double_as_longlong(d);
}

// ---------------- k_count: degrees + hist (+fused scan) + weight sumsq -------
// blocks [0, EDGE_BLOCKS): edges; blocks [EDGE_BLOCKS, +64): weight sumsq
__global__ void __launch_bounds__(256) k_count(const int* __restrict__ ei,
                                               const int* __restrict__ et,
                                               const float* __restrict__ wf,
                                               const float* __restrict__ wb) {
    int b = blockIdx.x;
    if (b < EDGE_BLOCKS) {
        __shared__ int sh[NUM_RELS];
        __shared__ int isLast;
        if (threadIdx.x < NUM_RELS) sh[threadIdx.x] = 0;
        __syncthreads();
        int e = b * 256 + threadIdx.x;
        if (e < N_EDGES) {
            atomicAdd(&G_DEG_SRC[ei[e]], 1);
            atomicAdd(&G_DEG_DST[ei[N_EDGES + e]], 1);
            atomicAdd(&sh[et[e]], 1);
        }
        __syncthreads();
        if (threadIdx.x < NUM_RELS && sh[threadIdx.x])
            atomicAdd(&G_HIST[threadIdx.x], sh[threadIdx.x]);
        __threadfence();
        if (threadIdx.x == 0)
            isLast = (atomicAdd(G_TICKET, 1) == EDGE_BLOCKS - 1);
        __syncthreads();
        if (isLast && threadIdx.x < NUM_RELS) {
            __threadfence();
            int t = threadIdx.x;
            int s = G_HIST[t];
            #pragma unroll
            for (int d = 1; d < 32; d <<= 1) {
                int n = __shfl_up_sync(0xffffffffu, s, d);
                if (t >= d) s += n;
            }
            g_off[t + 1] = s;
            if (t == 0) g_off[0] = 0;
        }
    } else {
        int m = b - EDGE_BLOCKS;   // 0..63
        const float4* src = (const float4*)((m < NUM_RELS)
                            ? (wf + (size_t)m * 4096)
                            : (wb + (size_t)(m - NUM_RELS) * 4096));
        __shared__ float red[8];
        float s = 0.f;
        #pragma unroll
        for (int j = 0; j < 4; j++) {
            float4 v = src[threadIdx.x + j * 256];
            s += v.x * v.x + v.y * v.y + v.z * v.z + v.w * v.w;
        }
        #pragma unroll
        for (int dd = 16; dd > 0; dd >>= 1) s += __shfl_xor_sync(0xffffffffu, s, dd);
        if ((threadIdx.x & 31) == 0) red[threadIdx.x >> 5] = s;
        __syncthreads();
        if (threadIdx.x == 0) {
            float tot = 0.f;
            #pragma unroll
            for (int w = 0; w < 8; w++) tot += red[w];
            g_wscale[m] = 1.0f / (sqrtf(tot) + 0.01f);
        }
    }
}

// ---------------- k_scatter: block-aggregated counting sort -> compact bkts --
__global__ void __launch_bounds__(256) k_scatter(const int* __restrict__ ei,
                                                 const int* __restrict__ et) {
    __shared__ int lh[NUM_RELS];
    __shared__ int lbase[NUM_RELS];
    if (threadIdx.x < NUM_RELS) lh[threadIdx.x] = 0;
    __syncthreads();
    int e = blockIdx.x * blockDim.x + threadIdx.x;
    int t = -1, myrank = 0;
    if (e < N_EDGES) {
        t = et[e];
        myrank = atomicAdd(&lh[t], 1);
    }
    __syncthreads();
    if (threadIdx.x < NUM_RELS) {
        int c = lh[threadIdx.x];
        lbase[threadIdx.x] = c ? atomicAdd(&G_CURSOR[threadIdx.x], c) : 0;
    }
    __syncthreads();
    if (e < N_EDGES) {
        int p = g_off[t] + lbase[t] + myrank;
        g_esrc[p] = ei[e];
        g_edst[p] = ei[N_EDGES + e];
    }
}

// ---------------- k_linear: 8 lanes per node, coalesced ----------------------
__global__ void __launch_bounds__(256) k_linear(const float* __restrict__ x,
                                                const float* __restrict__ lw,
                                                const float* __restrict__ lb,
                                                float* __restrict__ out) {
    __shared__ __align__(16) float Ls[64 * 64];   // Ls[i*64+o] = lw[o*64+i]
    __shared__ float Bs[64];
    for (int j = threadIdx.x; j < 4096; j += 256) {
        int o = j >> 6, i = j & 63;
        Ls[i * 64 + o] = lw[j];
    }
    if (threadIdx.x < 64) Bs[threadIdx.x] = lb[threadIdx.x];
    __syncthreads();

    int gid = threadIdx.x >> 3;          // group 0..31
    int l8  = threadIdx.x & 7;           // lane within group
    int n   = blockIdx.x * 32 + gid;
    if (n >= N_NODES) return;

    // each lane holds 8 consecutive x values of this node's row
    const float4* xp = (const float4*)(x + (size_t)n * 64 + l8 * 8);
    float4 xv0 = xp[0], xv1 = xp[1];
    float xs[8] = {xv0.x, xv0.y, xv0.z, xv0.w, xv1.x, xv1.y, xv1.z, xv1.w};

    unsigned long long acc[4] = {0ull, 0ull, 0ull, 0ull};
    const float* Wb = Ls + l8 * 8;       // this lane's 8 output columns
    #pragma unroll
    for (int i = 0; i < 64; i++) {
        float xi = __shfl_sync(0xffffffffu, xs[i & 7], i >> 3, 8);
        unsigned long long xi2 = pack2(xi);
        const double2* wr = (const double2*)(Wb + i * 64);
        double2 w0 = wr[0], w1 = wr[1];
        fma2(acc[0], xi2, d_as_ull(w0.x));
        fma2(acc[1], xi2, d_as_ull(w0.y));
        fma2(acc[2], xi2, d_as_ull(w1.x));
        fma2(acc[3], xi2, d_as_ull(w1.y));
    }

    float a0, a1, a2, a3, a4, a5, a6, a7;
    unpack2(acc[0], a0, a1); unpack2(acc[1], a2, a3);
    unpack2(acc[2], a4, a5); unpack2(acc[3], a6, a7);
    const float4* B4 = (const float4*)(Bs + l8 * 8);
    float4 b0 = B4[0], b1 = B4[1];
    float4* op = (float4*)(out + (size_t)n * 64 + l8 * 8);
    op[0] = make_float4(a0 + b0.x, a1 + b0.y, a2 + b0.z, a3 + b0.w);
    op[1] = make_float4(a4 + b1.x, a5 + b1.y, a6 + b1.z, a7 + b1.w);
}

// ---------------- k_edge: 8 lanes per edge ----------------------------------
__global__ void __launch_bounds__(256) k_edge(const float* __restrict__ x,
                                              const float* __restrict__ wf,
                                              const float* __restrict__ wb,
                                              float* __restrict__ out) {
    __shared__ __align__(16) float Ws[4096];
    int b = blockIdx.x;
    int dir = b & 1;
    int t = (b >> 1) & 31;
    int chunk = b >> 6;                  // 0..CHUNKS-1

    const float4* Wg = (const float4*)(((dir == 0) ? wf : wb) + (size_t)t * 4096);
    float4* Ws4w = (float4*)Ws;
    for (int j = threadIdx.x; j < 1024; j += 256) Ws4w[j] = Wg[j];
    __syncthreads();

    int start = g_off[t], end = g_off[t + 1];
    float wsc = g_wscale[dir * NUM_RELS + t];
    int gid = threadIdx.x >> 3;          // 0..31
    int l8  = threadIdx.x & 7;
    const float* Wb = Ws + l8 * 8;

    for (int idx = start + chunk * 32 + gid; idx < end; idx += 32 * CHUNKS) {
        int es = g_esrc[idx];            // broadcast within group
        int ed = g_edst[idx];
        int row, onode, deg;
        if (dir == 0) { row = es; onode = ed; deg = G_DEG_SRC[row]; }
        else          { row = ed; onode = es; deg = G_DEG_DST[row]; }
        float scale = wsc * __fdividef(1.0f, (float)(deg + 1));

        const float4* xp = (const float4*)(x + (size_t)row * 64 + l8 * 8);
        float4 xv0 = xp[0], xv1 = xp[1];
        float xs[8] = {xv0.x, xv0.y, xv0.z, xv0.w, xv1.x, xv1.y, xv1.z, xv1.w};

        unsigned long long acc[4] = {0ull, 0ull, 0ull, 0ull};
        #pragma unroll
        for (int i = 0; i < 64; i++) {
            float xi = __shfl_sync(0xffffffffu, xs[i & 7], i >> 3, 8);
            unsigned long long xi2 = pack2(xi);
            const double2* wr = (const double2*)(Wb + i * 64);
            double2 w0 = wr[0], w1 = wr[1];
            fma2(acc[0], xi2, d_as_ull(w0.x));
            fma2(acc[1], xi2, d_as_ull(w0.y));
            fma2(acc[2], xi2, d_as_ull(w1.x));
            fma2(acc[3], xi2, d_as_ull(w1.y));
        }

        float a0, a1, a2, a3, a4, a5, a6, a7;
        unpack2(acc[0], a0, a1); unpack2(acc[1], a2, a3);
        unpack2(acc[2], a4, a5); unpack2(acc[3], a6, a7);
        float* op = out + (size_t)onode * 64 + l8 * 8;
        asm volatile("red.global.add.v4.f32 [%0], {%1, %2, %3, %4};"
                     :: "l"(op), "f"(a0 * scale), "f"(a1 * scale),
                        "f"(a2 * scale), "f"(a3 * scale) : "memory");
        asm volatile("red.global.add.v4.f32 [%0], {%1, %2, %3, %4};"
                     :: "l"(op + 4), "f"(a4 * scale), "f"(a5 * scale),
                        "f"(a6 * scale), "f"(a7 * scale) : "memory");
    }
}

// ---------------- launch ----------------------------------------------------
extern "C" void kernel_launch(void* const* d_in, const int* in_sizes, int n_in,
                              void* d_out, int out_size) {
    const float* x   = (const float*)d_in[0];
    const int*   ei  = (const int*)d_in[1];     // [2, E] int32
    const int*   et  = (const int*)d_in[2];     // [E]    int32
    const float* wf  = (const float*)d_in[3];
    const float* wb  = (const float*)d_in[4];
    const float* lw  = (const float*)d_in[5];
    const float* lb  = (const float*)d_in[6];
    float*       out = (float*)d_out;

    (void)in_sizes; (void)n_in; (void)out_size;

    void* prepAddr = nullptr;
    cudaGetSymbolAddress(&prepAddr, g_prep);

    cudaStream_t sB;
    cudaEvent_t evRoot, evB;
    cudaStreamCreateWithFlags(&sB, cudaStreamNonBlocking);
    cudaEventCreateWithFlags(&evRoot, cudaEventDisableTiming);
    cudaEventCreateWithFlags(&evB, cudaEventDisableTiming);

    cudaEventRecord(evRoot, 0);
    cudaStreamWaitEvent(sB, evRoot, 0);

    // chain A: zero -> count(+scan, +wscale) -> scatter
    cudaMemsetAsync(prepAddr, 0, sizeof(int) * PREP_INTS, 0);
    k_count<<<EDGE_BLOCKS + 2 * NUM_RELS, 256>>>(ei, et, wf, wb);
    k_scatter<<<EDGE_BLOCKS, 256>>>(ei, et);

    // chain B: dense linear writes out
    k_linear<<<(N_NODES + 31) / 32, 256, 0, sB>>>(x, lw, lb, out);
    cudaEventRecord(evB, sB);

    cudaStreamWaitEvent(0, evB, 0);
    k_edge<<<2 * NUM_RELS * CHUNKS, 256>>>(x, wf, wb, out);

    cudaEventDestroy(evRoot);
    cudaEventDestroy(evB);
    cudaStreamDestroy(sB);
}

// round 7
// speedup vs baseline: 1.3966x; 1.3966x over previous
#include <cuda_runtime.h>
#include <math.h>

#define IN_C   64
#define OUT_C  64
#define NUM_RELS 32
#define N_NODES 20000
#define N_EDGES 50000
#define EDGE_BLOCKS ((N_EDGES + 255) / 256)     // 196
#define EC 7                                    // edge-chunk blocks per (dir,type)
#define EW 4                                    // warps per edge block
#define XPITCH 68                               // x stage pitch (floats), 16B-aligned, bank-safe

// ---------------- device scratch ----------------
// one contiguous zeroed region: [0,2N) degrees | hist 32 | cursor 32 | ticket
#define PREP_INTS (2 * N_NODES + NUM_RELS + NUM_RELS + 1)
__device__ __align__(16) int g_prep[PREP_INTS];
#define G_DEG_SRC  (g_prep)
#define G_DEG_DST  (g_prep + N_NODES)
#define G_HIST     (g_prep + 2 * N_NODES)
#define G_CURSOR   (g_prep + 2 * N_NODES + NUM_RELS)
#define G_TICKET   (g_prep + 2 * N_NODES + 2 * NUM_RELS)

__device__ int   g_off[NUM_RELS + 1];
__device__ float g_wscale[2 * NUM_RELS];   // 1/(||W||+0.01) per (dir,type)
__device__ int   g_esrc[N_EDGES];
__device__ int   g_edst[N_EDGES];

// ---- packed f32x2 helpers ----
__device__ __forceinline__ void fma2(unsigned long long& d,
                                     unsigned long long a, unsigned long long b) {
    asm("fma.rn.f32x2 %0, %1, %2, %0;" : "+l"(d) : "l"(a), "l"(b));
}
__device__ __forceinline__ unsigned long long pack2(float v) {
    unsigned long long r;
    asm("mov.b64 %0, {%1, %1};" : "=l"(r) : "f"(v));
    return r;
}
__device__ __forceinline__ void unpack2(unsigned long long v, float& lo, float& hi) {
    asm("mov.b64 {%0, %1}, %2;" : "=f"(lo), "=f"(hi) : "l"(v));
}
__device__ __forceinline__ unsigned long long d_as_ull(double d) {
    return __double_as_longlong(d);
}

// ---------------- k_count: degrees + hist (+fused scan) + weight sumsq -------
__global__ void __launch_bounds__(256) k_count(const int* __restrict__ ei,
                                               const int* __restrict__ et,
                                               const float* __restrict__ wf,
                                               const float* __restrict__ wb) {
    int b = blockIdx.x;
    if (b < EDGE_BLOCKS) {
        __shared__ int sh[NUM_RELS];
        __shared__ int isLast;
        if (threadIdx.x < NUM_RELS) sh[threadIdx.x] = 0;
        __syncthreads();
        int e = b * 256 + threadIdx.x;
        if (e < N_EDGES) {
            atomicAdd(&G_DEG_SRC[ei[e]], 1);
            atomicAdd(&G_DEG_DST[ei[N_EDGES + e]], 1);
            atomicAdd(&sh[et[e]], 1);
        }
        __syncthreads();
        if (threadIdx.x < NUM_RELS && sh[threadIdx.x])
            atomicAdd(&G_HIST[threadIdx.x], sh[threadIdx.x]);
        __threadfence();
        if (threadIdx.x == 0)
            isLast = (atomicAdd(G_TICKET, 1) == EDGE_BLOCKS - 1);
        __syncthreads();
        if (isLast && threadIdx.x < NUM_RELS) {
            __threadfence();
            int t = threadIdx.x;
            int s = G_HIST[t];
            #pragma unroll
            for (int d = 1; d < 32; d <<= 1) {
                int n = __shfl_up_sync(0xffffffffu, s, d);
                if (t >= d) s += n;
            }
            g_off[t + 1] = s;
            if (t == 0) g_off[0] = 0;
        }
    } else {
        int m = b - EDGE_BLOCKS;   // 0..63
        const float4* src = (const float4*)((m < NUM_RELS)
                            ? (wf + (size_t)m * 4096)
                            : (wb + (size_t)(m - NUM_RELS) * 4096));
        __shared__ float red[8];
        float s = 0.f;
        #pragma unroll
        for (int j = 0; j < 4; j++) {
            float4 v = src[threadIdx.x + j * 256];
            s += v.x * v.x + v.y * v.y + v.z * v.z + v.w * v.w;
        }
        #pragma unroll
        for (int dd = 16; dd > 0; dd >>= 1) s += __shfl_xor_sync(0xffffffffu, s, dd);
        if ((threadIdx.x & 31) == 0) red[threadIdx.x >> 5] = s;
        __syncthreads();
        if (threadIdx.x == 0) {
            float tot = 0.f;
            #pragma unroll
            for (int w = 0; w < 8; w++) tot += red[w];
            g_wscale[m] = 1.0f / (sqrtf(tot) + 0.01f);
        }
    }
}

// ---------------- k_scatter: block-aggregated counting sort -----------------
__global__ void __launch_bounds__(256) k_scatter(const int* __restrict__ ei,
                                                 const int* __restrict__ et) {
    __shared__ int lh[NUM_RELS];
    __shared__ int lbase[NUM_RELS];
    if (threadIdx.x < NUM_RELS) lh[threadIdx.x] = 0;
    __syncthreads();
    int e = blockIdx.x * blockDim.x + threadIdx.x;
    int t = -1, myrank = 0;
    if (e < N_EDGES) {
        t = et[e];
        myrank = atomicAdd(&lh[t], 1);
    }
    __syncthreads();
    if (threadIdx.x < NUM_RELS) {
        int c = lh[threadIdx.x];
        lbase[threadIdx.x] = c ? atomicAdd(&G_CURSOR[threadIdx.x], c) : 0;
    }
    __syncthreads();
    if (e < N_EDGES) {
        int p = g_off[t] + lbase[t] + myrank;
        g_esrc[p] = ei[e];
        g_edst[p] = ei[N_EDGES + e];
    }
}

// ---------------- k_linear: thread-per-node (proven R4 form) ----------------
__global__ void __launch_bounds__(256) k_linear(const float* __restrict__ x,
                                                const float* __restrict__ lw,
                                                const float* __restrict__ lb,
                                                float* __restrict__ out) {
    __shared__ __align__(16) float Ls[64 * 64];   // Ls[i*64+o] = lw[o*64+i]
    __shared__ float Bs[64];
    for (int j = threadIdx.x; j < 4096; j += 256) {
        int o = j >> 6, i = j & 63;
        Ls[i * 64 + o] = lw[j];
    }
    if (threadIdx.x < 64) Bs[threadIdx.x] = lb[threadIdx.x];
    __syncthreads();

    int n = blockIdx.x * 256 + threadIdx.x;
    if (n >= N_NODES) return;

    unsigned long long acc[32];
    #pragma unroll
    for (int k = 0; k < 32; k++) acc[k] = 0ull;

    const float4* xr = (const float4*)(x + (size_t)n * 64);
    #pragma unroll 1
    for (int i4 = 0; i4 < 16; i4++) {
        float4 v = xr[i4];
        float vs[4] = {v.x, v.y, v.z, v.w};
        #pragma unroll
        for (int j = 0; j < 4; j++) {
            unsigned long long vv = pack2(vs[j]);
            const double2* wrow = (const double2*)(Ls + ((i4 * 4 + j) << 6));
            #pragma unroll
            for (int o4 = 0; o4 < 16; o4++) {
                double2 w = wrow[o4];
                fma2(acc[2 * o4], vv, d_as_ull(w.x));
                fma2(acc[2 * o4 + 1], vv, d_as_ull(w.y));
            }
        }
    }
    float4* outr = (float4*)(out + (size_t)n * 64);
    const float4* B4 = (const float4*)Bs;
    #pragma unroll
    for (int o = 0; o < 16; o++) {
        float a0, a1, a2, a3;
        unpack2(acc[2 * o], a0, a1);
        unpack2(acc[2 * o + 1], a2, a3);
        float4 b = B4[o];
        outr[o] = make_float4(a0 + b.x, a1 + b.y, a2 + b.z, a3 + b.w);
    }
}

// ---------------- k_edge: register-tiled GEMM, 8 edges x 8 outs per thread ---
// dyn smem: Ws[4096] | xs[EW][32*XPITCH] | m_row[EW][32] | m_on[EW][32] | m_sc[EW][32]
__global__ void __launch_bounds__(128, 4) k_edge(const float* __restrict__ x,
                                                 const float* __restrict__ wf,
                                                 const float* __restrict__ wb,
                                                 float* __restrict__ out) {
    extern __shared__ __align__(16) float smem[];
    float* Ws = smem;                                // 4096 floats
    float* xs = smem + 4096;                         // EW*32*XPITCH
    int*   m_row = (int*)(xs + EW * 32 * XPITCH);    // EW*32
    int*   m_on  = m_row + EW * 32;                  // EW*32
    float* m_sc  = (float*)(m_on + EW * 32);         // EW*32

    int b = blockIdx.x;
    int dir = b & 1;
    int t = (b >> 1) & 31;
    int chunk = b >> 6;                              // 0..EC-1

    // stage W (raw weights; norm folded into scale)
    const float4* Wg = (const float4*)(((dir == 0) ? wf : wb) + (size_t)t * 4096);
    float4* Wsw = (float4*)Ws;
    for (int j = threadIdx.x; j < 1024; j += 128) Wsw[j] = Wg[j];
    __syncthreads();

    int start = g_off[t], end = g_off[t + 1];
    float wsc = g_wscale[dir * NUM_RELS + t];

    int wid  = threadIdx.x >> 5;
    int lane = threadIdx.x & 31;
    int tg = lane & 3;           // edge interleave group (stride-4)
    int og = lane >> 2;          // output group: cols og*8 .. og*8+7
    float* xw = xs + wid * 32 * XPITCH;
    int*   rw = m_row + wid * 32;
    int*   onw = m_on + wid * 32;
    float* scw = m_sc + wid * 32;

    int half = lane >> 4;        // gather: 2 rows per iteration
    int c    = lane & 15;        // float4 index within a row

    for (int base = start + (chunk * EW + wid) * 32; base < end;
         base += EC * EW * 32) {
        int nE = min(32, end - base);

        // ---- meta: one edge per lane ----
        int row = 0, onode = 0;
        float sc = 0.f;
        if (lane < nE) {
            int es = g_esrc[base + lane];
            int ed = g_edst[base + lane];
            row   = dir ? ed : es;
            onode = dir ? es : ed;
            int deg = dir ? G_DEG_DST[row] : G_DEG_SRC[row];
            sc = wsc * __fdividef(1.0f, (float)(deg + 1));
        }
        rw[lane] = row;
        onw[lane] = onode;
        scw[lane] = sc;
        __syncwarp();

        // ---- gather 32 x-rows, coalesced (16 lanes per row, 2 rows/iter) ----
        #pragma unroll
        for (int it = 0; it < 16; it++) {
            int r = it * 2 + half;
            int rg = rw[r];
            float4 v = *(const float4*)(x + (size_t)rg * 64 + c * 4);
            *(float4*)(xw + r * XPITCH + c * 4) = v;
        }
        __syncwarp();

        // ---- compute: 8 edges (stride-4 interleave) x 8 outs per thread ----
        unsigned long long acc[8][4];
        #pragma unroll
        for (int j = 0; j < 8; j++)
            #pragma unroll
            for (int p = 0; p < 4; p++) acc[j][p] = 0ull;

        #pragma unroll 2
        for (int c4 = 0; c4 < 16; c4++) {
            float4 xv[8];
            #pragma unroll
            for (int j = 0; j < 8; j++)
                xv[j] = *(const float4*)(xw + (4 * j + tg) * XPITCH + c4 * 4);
            #pragma unroll
            for (int r = 0; r < 4; r++) {
                const double2* wp = (const double2*)(Ws + (c4 * 4 + r) * 64 + og * 8);
                double2 w0 = wp[0], w1 = wp[1];
                unsigned long long b0 = d_as_ull(w0.x), b1 = d_as_ull(w0.y);
                unsigned long long b2 = d_as_ull(w1.x), b3 = d_as_ull(w1.y);
                #pragma unroll
                for (int j = 0; j < 8; j++) {
                    float xi = (r == 0) ? xv[j].x : (r == 1) ? xv[j].y
                             : (r == 2) ? xv[j].z : xv[j].w;
                    unsigned long long xi2 = pack2(xi);
                    fma2(acc[j][0], xi2, b0);
                    fma2(acc[j][1], xi2, b1);
                    fma2(acc[j][2], xi2, b2);
                    fma2(acc[j][3], xi2, b3);
                }
            }
        }

        // ---- epilogue: scale + coalesced red.v4 scatter ----
        #pragma unroll
        for (int j = 0; j < 8; j++) {
            int e = 4 * j + tg;
            if (e < nE) {
                float s = scw[e];
                int on = onw[e];
                float a0, a1, a2, a3, a4, a5, a6, a7;
                unpack2(acc[j][0], a0, a1);
                unpack2(acc[j][1], a2, a3);
                unpack2(acc[j][2], a4, a5);
                unpack2(acc[j][3], a6, a7);
                float* op = out + (size_t)on * 64 + og * 8;
                asm volatile("red.global.add.v4.f32 [%0], {%1, %2, %3, %4};"
                             :: "l"(op), "f"(a0 * s), "f"(a1 * s),
                                "f"(a2 * s), "f"(a3 * s) : "memory");
                asm volatile("red.global.add.v4.f32 [%0], {%1, %2, %3, %4};"
                             :: "l"(op + 4), "f"(a4 * s), "f"(a5 * s),
                                "f"(a6 * s), "f"(a7 * s) : "memory");
            }
        }
        __syncwarp();
    }
}

#define EDGE_SMEM ((4096 + EW * 32 * XPITCH + 2 * EW * 32) * 4 + EW * 32 * 4)

// ---------------- launch ----------------------------------------------------
extern "C" void kernel_launch(void* const* d_in, const int* in_sizes, int n_in,
                              void* d_out, int out_size) {
    const float* x   = (const float*)d_in[0];
    const int*   ei  = (const int*)d_in[1];     // [2, E] int32
    const int*   et  = (const int*)d_in[2];     // [E]    int32
    const float* wf  = (const float*)d_in[3];
    const float* wb  = (const float*)d_in[4];
    const float* lw  = (const float*)d_in[5];
    const float* lb  = (const float*)d_in[6];
    float*       out = (float*)d_out;

    (void)in_sizes; (void)n_in; (void)out_size;

    void* prepAddr = nullptr;
    cudaGetSymbolAddress(&prepAddr, g_prep);
    cudaFuncSetAttribute(k_edge, cudaFuncAttributeMaxDynamicSharedMemorySize,
                         EDGE_SMEM);

    cudaStream_t sB;
    cudaEvent_t evRoot, evB;
    cudaStreamCreateWithFlags(&sB, cudaStreamNonBlocking);
    cudaEventCreateWithFlags(&evRoot, cudaEventDisableTiming);
    cudaEventCreateWithFlags(&evB, cudaEventDisableTiming);

    cudaEventRecord(evRoot, 0);
    cudaStreamWaitEvent(sB, evRoot, 0);

    // chain A: zero -> count(+scan, +wscale) -> scatter
    cudaMemsetAsync(prepAddr, 0, sizeof(int) * PREP_INTS, 0);
    k_count<<<EDGE_BLOCKS + 2 * NUM_RELS, 256>>>(ei, et, wf, wb);
    k_scatter<<<EDGE_BLOCKS, 256>>>(ei, et);

    // chain B: dense linear writes out
    k_linear<<<(N_NODES + 255) / 256, 256, 0, sB>>>(x, lw, lb, out);
    cudaEventRecord(evB, sB);

    cudaStreamWaitEvent(0, evB, 0);
    k_edge<<<2 * NUM_RELS * EC, 128, EDGE_SMEM>>>(x, wf, wb, out);

    cudaEventDestroy(evRoot);
    cudaEventDestroy(evB);
    cudaStreamDestroy(sB);
}

// round 8
// speedup vs baseline: 1.8304x; 1.3106x over previous
#include <cuda_runtime.h>
#include <math.h>

#define IN_C   64
#define OUT_C  64
#define NUM_RELS 32
#define N_NODES 20000
#define N_EDGES 50000
#define EDGE_BLOCKS ((N_EDGES + 255) / 256)       // 196
#define WSCALE_BLOCKS (2 * NUM_RELS)              // 64
#define LIN_BLOCKS ((N_NODES + 255) / 256)        // 79
#define PREP_GRID (EDGE_BLOCKS + WSCALE_BLOCKS + LIN_BLOCKS)
#define EC 10                                     // edge-chunk blocks per (dir,type)
#define EW 4                                      // warps per edge block
#define XPITCH 68                                 // stage pitch (floats)

// ---------------- device scratch ----------------
// contiguous zeroed region: degrees | hist | cursor | ticket | flag
#define PREP_INTS (2 * N_NODES + 2 * NUM_RELS + 2)
__device__ __align__(16) int g_prep[PREP_INTS];
#define G_DEG_SRC  (g_prep)
#define G_DEG_DST  (g_prep + N_NODES)
#define G_HIST     (g_prep + 2 * N_NODES)
#define G_CURSOR   (g_prep + 2 * N_NODES + NUM_RELS)
#define G_TICKET   (g_prep + 2 * N_NODES + 2 * NUM_RELS)
#define G_FLAG     (g_prep + 2 * N_NODES + 2 * NUM_RELS + 1)

__device__ int   g_off[NUM_RELS + 1];
__device__ float g_wscale[2 * NUM_RELS];
__device__ int   g_esrc[N_EDGES];
__device__ int   g_edst[N_EDGES];

// ---- packed f32x2 helpers ----
__device__ __forceinline__ void fma2(unsigned long long& d,
                                     unsigned long long a, unsigned long long b) {
    asm("fma.rn.f32x2 %0, %1, %2, %0;" : "+l"(d) : "l"(a), "l"(b));
}
__device__ __forceinline__ unsigned long long pack2(float v) {
    unsigned long long r;
    asm("mov.b64 %0, {%1, %1};" : "=l"(r) : "f"(v));
    return r;
}
__device__ __forceinline__ void unpack2(unsigned long long v, float& lo, float& hi) {
    asm("mov.b64 {%0, %1}, %2;" : "=f"(lo), "=f"(hi) : "l"(v));
}
__device__ __forceinline__ unsigned long long d_as_ull(double d) {
    return __double_as_longlong(d);
}

// ---------------- k_prep: count+scan+scatter | wscale | linear (one launch) --
__global__ void __launch_bounds__(256, 3) k_prep(const int* __restrict__ ei,
                                                 const int* __restrict__ et,
                                                 const float* __restrict__ wf,
                                                 const float* __restrict__ wb,
                                                 const float* __restrict__ x,
                                                 const float* __restrict__ lw,
                                                 const float* __restrict__ lb,
                                                 float* __restrict__ out) {
    int b = blockIdx.x;
    if (b < EDGE_BLOCKS) {
        // ---- phase 1: degrees + block-agg histogram ----
        __shared__ int sh[NUM_RELS];
        __shared__ int lbase[NUM_RELS];
        __shared__ int isLast;
        if (threadIdx.x < NUM_RELS) sh[threadIdx.x] = 0;
        __syncthreads();
        int e = b * 256 + threadIdx.x;
        int s = 0, d = 0, t = -1;
        if (e < N_EDGES) {
            s = ei[e];
            d = ei[N_EDGES + e];
            t = et[e];
            atomicAdd(&G_DEG_SRC[s], 1);
            atomicAdd(&G_DEG_DST[d], 1);
            atomicAdd(&sh[t], 1);
        }
        __syncthreads();
        if (threadIdx.x < NUM_RELS && sh[threadIdx.x])
            atomicAdd(&G_HIST[threadIdx.x], sh[threadIdx.x]);
        __threadfence();
        if (threadIdx.x == 0)
            isLast = (atomicAdd(G_TICKET, 1) == EDGE_BLOCKS - 1);
        __syncthreads();
        // ---- last block: 32-bin exclusive scan, release flag ----
        if (isLast && threadIdx.x < 32) {
            int tt = threadIdx.x;
            int v = atomicAdd(&G_HIST[tt], 0);
            #pragma unroll
            for (int dd = 1; dd < 32; dd <<= 1) {
                int n = __shfl_up_sync(0xffffffffu, v, dd);
                if (tt >= dd) v += n;
            }
            g_off[tt + 1] = v;
            if (tt == 0) g_off[0] = 0;
            __syncwarp();
            __threadfence();
            if (tt == 0) atomicExch(G_FLAG, 1);
        }
        // ---- all edge blocks wait for offsets ----
        if (threadIdx.x == 0) {
            while (atomicAdd(G_FLAG, 0) == 0) __nanosleep(64);
        }
        __syncthreads();
        // ---- phase 2: block-aggregated scatter ----
        if (threadIdx.x < NUM_RELS) sh[threadIdx.x] = 0;
        __syncthreads();
        int myrank = 0;
        if (e < N_EDGES) myrank = atomicAdd(&sh[t], 1);
        __syncthreads();
        if (threadIdx.x < NUM_RELS) {
            int c = sh[threadIdx.x];
            lbase[threadIdx.x] = c ? atomicAdd(&G_CURSOR[threadIdx.x], c) : 0;
        }
        __syncthreads();
        if (e < N_EDGES) {
            int p = __ldcg(&g_off[t]) + lbase[t] + myrank;
            g_esrc[p] = s;
            g_edst[p] = d;
        }
    } else if (b < EDGE_BLOCKS + WSCALE_BLOCKS) {
        // ---- weight sumsq -> wscale ----
        int m = b - EDGE_BLOCKS;   // 0..63
        const float4* src = (const float4*)((m < NUM_RELS)
                            ? (wf + (size_t)m * 4096)
                            : (wb + (size_t)(m - NUM_RELS) * 4096));
        __shared__ float red[8];
        float sq = 0.f;
        #pragma unroll
        for (int j = 0; j < 4; j++) {
            float4 v = src[threadIdx.x + j * 256];
            sq += v.x * v.x + v.y * v.y + v.z * v.z + v.w * v.w;
        }
        #pragma unroll
        for (int dd = 16; dd > 0; dd >>= 1) sq += __shfl_xor_sync(0xffffffffu, sq, dd);
        if ((threadIdx.x & 31) == 0) red[threadIdx.x >> 5] = sq;
        __syncthreads();
        if (threadIdx.x == 0) {
            float tot = 0.f;
            #pragma unroll
            for (int w = 0; w < 8; w++) tot += red[w];
            g_wscale[m] = 1.0f / (sqrtf(tot) + 0.01f);
        }
    } else {
        // ---- dense linear: out = x @ lw^T + lb ----
        __shared__ __align__(16) float Ls[64 * 64];
        __shared__ float Bs[64];
        for (int j = threadIdx.x; j < 4096; j += 256) {
            int o = j >> 6, i = j & 63;
            Ls[i * 64 + o] = lw[j];
        }
        if (threadIdx.x < 64) Bs[threadIdx.x] = lb[threadIdx.x];
        __syncthreads();

        int n = (b - EDGE_BLOCKS - WSCALE_BLOCKS) * 256 + threadIdx.x;
        if (n >= N_NODES) return;

        unsigned long long acc[32];
        #pragma unroll
        for (int k = 0; k < 32; k++) acc[k] = 0ull;

        const float4* xr = (const float4*)(x + (size_t)n * 64);
        #pragma unroll 1
        for (int i4 = 0; i4 < 16; i4++) {
            float4 v = xr[i4];
            float vs[4] = {v.x, v.y, v.z, v.w};
            #pragma unroll
            for (int j = 0; j < 4; j++) {
                unsigned long long vv = pack2(vs[j]);
                const double2* wrow = (const double2*)(Ls + ((i4 * 4 + j) << 6));
                #pragma unroll
                for (int o4 = 0; o4 < 16; o4++) {
                    double2 w = wrow[o4];
                    fma2(acc[2 * o4], vv, d_as_ull(w.x));
                    fma2(acc[2 * o4 + 1], vv, d_as_ull(w.y));
                }
            }
        }
        float4* outr = (float4*)(out + (size_t)n * 64);
        const float4* B4 = (const float4*)Bs;
        #pragma unroll
        for (int o = 0; o < 16; o++) {
            float a0, a1, a2, a3;
            unpack2(acc[2 * o], a0, a1);
            unpack2(acc[2 * o + 1], a2, a3);
            float4 bb = B4[o];
            outr[o] = make_float4(a0 + bb.x, a1 + bb.y, a2 + bb.z, a3 + bb.w);
        }
    }
}

// ---------------- k_edge: 4 edges x 8 outs per thread, 16-edge warp tiles ----
// dyn smem: Ws[4096] | xs[EW][16*XPITCH] | meta
__global__ void __launch_bounds__(128, 6) k_edge(const float* __restrict__ x,
                                                 const float* __restrict__ wf,
                                                 const float* __restrict__ wb,
                                                 float* __restrict__ out) {
    extern __shared__ __align__(16) float smem[];
    float* Ws = smem;                                 // 4096 floats
    float* xs = smem + 4096;                          // EW*16*XPITCH
    int*   m_row = (int*)(xs + EW * 16 * XPITCH);     // EW*16
    int*   m_on  = m_row + EW * 16;
    float* m_sc  = (float*)(m_on + EW * 16);

    int b = blockIdx.x;
    int dir = b & 1;
    int t = (b >> 1) & 31;
    int chunk = b >> 6;                               // 0..EC-1

    const float4* Wg = (const float4*)(((dir == 0) ? wf : wb) + (size_t)t * 4096);
    float4* Wsw = (float4*)Ws;
    for (int j = threadIdx.x; j < 1024; j += 128) Wsw[j] = Wg[j];
    __syncthreads();

    int start = g_off[t], end = g_off[t + 1];
    float wsc = g_wscale[dir * NUM_RELS + t];

    int wid  = threadIdx.x >> 5;
    int lane = threadIdx.x & 31;
    int tg = lane & 3;            // edge group: edges tg, tg+4, tg+8, tg+12
    int og = lane >> 2;           // output cols og*8 .. og*8+7
    float* xw = xs + wid * 16 * XPITCH;
    int*   rw  = m_row + wid * 16;
    int*   onw = m_on + wid * 16;
    float* scw = m_sc + wid * 16;

    int half = lane >> 4;         // gather helper: 2 rows per iter
    int c    = lane & 15;

    for (int base = start + (chunk * EW + wid) * 16; base < end;
         base += EC * EW * 16) {
        int nE = min(16, end - base);

        // ---- meta: one edge per lane (lanes 0..15) ----
        if (lane < 16) {
            int row = 0, onode = 0;
            float sc = 0.f;
            if (lane < nE) {
                int es = g_esrc[base + lane];
                int ed = g_edst[base + lane];
                row   = dir ? ed : es;
                onode = dir ? es : ed;
                int deg = dir ? G_DEG_DST[row] : G_DEG_SRC[row];
                sc = wsc * __fdividef(1.0f, (float)(deg + 1));
            }
            rw[lane] = row;
            onw[lane] = onode;
            scw[lane] = sc;
        }
        __syncwarp();

        // ---- gather 16 x-rows, coalesced (16 lanes/row, 2 rows/iter) ----
        #pragma unroll
        for (int it = 0; it < 8; it++) {
            int r = it * 2 + half;
            int rg = rw[r];
            float4 v = *(const float4*)(x + (size_t)rg * 64 + c * 4);
            *(float4*)(xw + r * XPITCH + c * 4) = v;
        }
        __syncwarp();

        // ---- compute: 4 edges x 8 outs per thread ----
        unsigned long long acc[4][4];
        #pragma unroll
        for (int j = 0; j < 4; j++)
            #pragma unroll
            for (int p = 0; p < 4; p++) acc[j][p] = 0ull;

        #pragma unroll 4
        for (int c4 = 0; c4 < 16; c4++) {
            float4 xv[4];
            #pragma unroll
            for (int j = 0; j < 4; j++)
                xv[j] = *(const float4*)(xw + (4 * j + tg) * XPITCH + c4 * 4);
            #pragma unroll
            for (int r = 0; r < 4; r++) {
                const double2* wp = (const double2*)(Ws + (c4 * 4 + r) * 64 + og * 8);
                double2 w0 = wp[0], w1 = wp[1];
                unsigned long long b0 = d_as_ull(w0.x), b1 = d_as_ull(w0.y);
                unsigned long long b2 = d_as_ull(w1.x), b3 = d_as_ull(w1.y);
                #pragma unroll
                for (int j = 0; j < 4; j++) {
                    float xi = (r == 0) ? xv[j].x : (r == 1) ? xv[j].y
                             : (r == 2) ? xv[j].z : xv[j].w;
                    unsigned long long xi2 = pack2(xi);
                    fma2(acc[j][0], xi2, b0);
                    fma2(acc[j][1], xi2, b1);
                    fma2(acc[j][2], xi2, b2);
                    fma2(acc[j][3], xi2, b3);
                }
            }
        }

        // ---- epilogue: scale + coalesced red.v4 scatter ----
        #pragma unroll
        for (int j = 0; j < 4; j++) {
            int e = 4 * j + tg;
            if (e < nE) {
                float s = scw[e];
                int on = onw[e];
                float a0, a1, a2, a3, a4, a5, a6, a7;
                unpack2(acc[j][0], a0, a1);
                unpack2(acc[j][1], a2, a3);
                unpack2(acc[j][2], a4, a5);
                unpack2(acc[j][3], a6, a7);
                float* op = out + (size_t)on * 64 + og * 8;
                asm volatile("red.global.add.v4.f32 [%0], {%1, %2, %3, %4};"
                             :: "l"(op), "f"(a0 * s), "f"(a1 * s),
                                "f"(a2 * s), "f"(a3 * s) : "memory");
                asm volatile("red.global.add.v4.f32 [%0], {%1, %2, %3, %4};"
                             :: "l"(op + 4), "f"(a4 * s), "f"(a5 * s),
                                "f"(a6 * s), "f"(a7 * s) : "memory");
            }
        }
        __syncwarp();
    }
}

#define EDGE_SMEM ((4096 + EW * 16 * XPITCH) * 4 + EW * 16 * 12)

// ---------------- launch: memset -> prep -> edge (3 nodes) ------------------
extern "C" void kernel_launch(void* const* d_in, const int* in_sizes, int n_in,
                              void* d_out, int out_size) {
    const float* x   = (const float*)d_in[0];
    const int*   ei  = (const int*)d_in[1];     // [2, E] int32
    const int*   et  = (const int*)d_in[2];     // [E]    int32
    const float* wf  = (const float*)d_in[3];
    const float* wb  = (const float*)d_in[4];
    const float* lw  = (const float*)d_in[5];
    const float* lb  = (const float*)d_in[6];
    float*       out = (float*)d_out;

    (void)in_sizes; (void)n_in; (void)out_size;

    void* prepAddr = nullptr;
    cudaGetSymbolAddress(&prepAddr, g_prep);
    cudaFuncSetAttribute(k_edge, cudaFuncAttributeMaxDynamicSharedMemorySize,
                         EDGE_SMEM);

    cudaMemsetAsync(prepAddr, 0, sizeof(int) * PREP_INTS, 0);
    k_prep<<<PREP_GRID, 256>>>(ei, et, wf, wb, x, lw, lb, out);
    k_edge<<<2 * NUM_RELS * EC, 128, EDGE_SMEM>>>(x, wf, wb, out);
}

// round 9
// speedup vs baseline: 2.4870x; 1.3587x over previous
#include <cuda_runtime.h>
#include <math.h>

#define IN_C   64
#define OUT_C  64
#define NUM_RELS 32
#define N_NODES 20000
#define N_EDGES 50000
#define EDGE_BLOCKS ((N_EDGES + 255) / 256)       // 196
#define WSCALE_BLOCKS (2 * NUM_RELS)              // 64
#define EC 13                                     // edge-chunk blocks per (dir,type)
#define EW 4                                      // warps per edge block
#define XPITCH 68
#define LIN_BLOCKS ((N_NODES + 127) / 128)        // 157 (128-thread blocks)

// ---------------- device scratch ----------------
#define PREP_INTS (2 * N_NODES + 2 * NUM_RELS + 1)
__device__ __align__(16) int g_prep[PREP_INTS];
#define G_DEG_SRC  (g_prep)
#define G_DEG_DST  (g_prep + N_NODES)
#define G_HIST     (g_prep + 2 * N_NODES)
#define G_CURSOR   (g_prep + 2 * N_NODES + NUM_RELS)
#define G_TICKET   (g_prep + 2 * N_NODES + 2 * NUM_RELS)

__device__ int   g_off[NUM_RELS + 1];
__device__ float g_wscale[2 * NUM_RELS];
__device__ int   g_esrc[N_EDGES];
__device__ int   g_edst[N_EDGES];

// ---- packed f32x2 helpers ----
__device__ __forceinline__ void fma2(unsigned long long& d,
                                     unsigned long long a, unsigned long long b) {
    asm("fma.rn.f32x2 %0, %1, %2, %0;" : "+l"(d) : "l"(a), "l"(b));
}
__device__ __forceinline__ unsigned long long pack2(float v) {
    unsigned long long r;
    asm("mov.b64 %0, {%1, %1};" : "=l"(r) : "f"(v));
    return r;
}
__device__ __forceinline__ void unpack2(unsigned long long v, float& lo, float& hi) {
    asm("mov.b64 {%0, %1}, %2;" : "=f"(lo), "=f"(hi) : "l"(v));
}
__device__ __forceinline__ unsigned long long d_as_ull(double d) {
    return __double_as_longlong(d);
}

// ---------------- k_count: degrees + hist + tail scan | wscale --------------
__global__ void __launch_bounds__(256) k_count(const int* __restrict__ ei,
                                               const int* __restrict__ et,
                                               const float* __restrict__ wf,
                                               const float* __restrict__ wb) {
    int b = blockIdx.x;
    if (b < EDGE_BLOCKS) {
        __shared__ int sh[NUM_RELS];
        __shared__ int isLast;
        if (threadIdx.x < NUM_RELS) sh[threadIdx.x] = 0;
        __syncthreads();
        int e = b * 256 + threadIdx.x;
        if (e < N_EDGES) {
            atomicAdd(&G_DEG_SRC[ei[e]], 1);
            atomicAdd(&G_DEG_DST[ei[N_EDGES + e]], 1);
            atomicAdd(&sh[et[e]], 1);
        }
        __syncthreads();
        if (threadIdx.x < NUM_RELS && sh[threadIdx.x])
            atomicAdd(&G_HIST[threadIdx.x], sh[threadIdx.x]);
        __threadfence();
        if (threadIdx.x == 0)
            isLast = (atomicAdd(G_TICKET, 1) == EDGE_BLOCKS - 1);
        __syncthreads();
        if (isLast && threadIdx.x < 32) {
            int t = threadIdx.x;
            int s = atomicAdd(&G_HIST[t], 0);
            #pragma unroll
            for (int d = 1; d < 32; d <<= 1) {
                int n = __shfl_up_sync(0xffffffffu, s, d);
                if (t >= d) s += n;
            }
            g_off[t + 1] = s;
            if (t == 0) g_off[0] = 0;
        }
    } else {
        int m = b - EDGE_BLOCKS;   // 0..63
        const float4* src = (const float4*)((m < NUM_RELS)
                            ? (wf + (size_t)m * 4096)
                            : (wb + (size_t)(m - NUM_RELS) * 4096));
        __shared__ float red[8];
        float sq = 0.f;
        #pragma unroll
        for (int j = 0; j < 4; j++) {
            float4 v = src[threadIdx.x + j * 256];
            sq += v.x * v.x + v.y * v.y + v.z * v.z + v.w * v.w;
        }
        #pragma unroll
        for (int dd = 16; dd > 0; dd >>= 1) sq += __shfl_xor_sync(0xffffffffu, sq, dd);
        if ((threadIdx.x & 31) == 0) red[threadIdx.x >> 5] = sq;
        __syncthreads();
        if (threadIdx.x == 0) {
            float tot = 0.f;
            #pragma unroll
            for (int w = 0; w < 8; w++) tot += red[w];
            g_wscale[m] = 1.0f / (sqrtf(tot) + 0.01f);
        }
    }
}

// ---------------- k_scatter: block-aggregated counting sort -----------------
__global__ void __launch_bounds__(256) k_scatter(const int* __restrict__ ei,
                                                 const int* __restrict__ et) {
    __shared__ int lh[NUM_RELS];
    __shared__ int lbase[NUM_RELS];
    if (threadIdx.x < NUM_RELS) lh[threadIdx.x] = 0;
    __syncthreads();
    int e = blockIdx.x * blockDim.x + threadIdx.x;
    int t = -1, myrank = 0;
    if (e < N_EDGES) {
        t = et[e];
        myrank = atomicAdd(&lh[t], 1);
    }
    __syncthreads();
    if (threadIdx.x < NUM_RELS) {
        int c = lh[threadIdx.x];
        lbase[threadIdx.x] = c ? atomicAdd(&G_CURSOR[threadIdx.x], c) : 0;
    }
    __syncthreads();
    if (e < N_EDGES) {
        int p = g_off[t] + lbase[t] + myrank;
        g_esrc[p] = ei[e];
        g_edst[p] = ei[N_EDGES + e];
    }
}

// ---------------- k_edge: linear blocks + edge blocks in one grid -----------
// out is pre-zeroed; ALL contributions (linear, bias, messages) via red.add.
// blocks [0, LIN_BLOCKS): dense linear, 128 nodes per block
// blocks [LIN_BLOCKS, +2*32*EC): edge tiles (4 edges x 8 outs per thread)
__global__ void __launch_bounds__(128, 6) k_edge(const float* __restrict__ x,
                                                 const float* __restrict__ wf,
                                                 const float* __restrict__ wb,
                                                 const float* __restrict__ lw,
                                                 const float* __restrict__ lb,
                                                 float* __restrict__ out) {
    extern __shared__ __align__(16) float smem[];

    if (blockIdx.x < LIN_BLOCKS) {
        // ================= dense linear =================
        float* Ls = smem;             // 4096 floats, Ls[i*64+o] = lw[o*64+i]
        float* Bs = smem + 4096;      // 64
        for (int j = threadIdx.x; j < 4096; j += 128) {
            int o = j >> 6, i = j & 63;
            Ls[i * 64 + o] = lw[j];
        }
        if (threadIdx.x < 64) Bs[threadIdx.x] = lb[threadIdx.x];
        __syncthreads();

        int n = blockIdx.x * 128 + threadIdx.x;
        if (n >= N_NODES) return;

        unsigned long long acc[32];
        #pragma unroll
        for (int k = 0; k < 32; k++) acc[k] = 0ull;

        const float4* xr = (const float4*)(x + (size_t)n * 64);
        #pragma unroll 1
        for (int i4 = 0; i4 < 16; i4++) {
            float4 v = xr[i4];
            float vs[4] = {v.x, v.y, v.z, v.w};
            #pragma unroll
            for (int j = 0; j < 4; j++) {
                unsigned long long vv = pack2(vs[j]);
                const double2* wrow = (const double2*)(Ls + ((i4 * 4 + j) << 6));
                #pragma unroll
                for (int o4 = 0; o4 < 16; o4++) {
                    double2 w = wrow[o4];
                    fma2(acc[2 * o4], vv, d_as_ull(w.x));
                    fma2(acc[2 * o4 + 1], vv, d_as_ull(w.y));
                }
            }
        }
        float* op = out + (size_t)n * 64;
        const float4* B4 = (const float4*)Bs;
        #pragma unroll
        for (int o = 0; o < 16; o++) {
            float a0, a1, a2, a3;
            unpack2(acc[2 * o], a0, a1);
            unpack2(acc[2 * o + 1], a2, a3);
            float4 bb = B4[o];
            asm volatile("red.global.add.v4.f32 [%0], {%1, %2, %3, %4};"
                         :: "l"(op + o * 4), "f"(a0 + bb.x), "f"(a1 + bb.y),
                            "f"(a2 + bb.z), "f"(a3 + bb.w) : "memory");
        }
        return;
    }

    // ================= edge tiles =================
    float* Ws = smem;                                 // 4096 floats
    float* xs = smem + 4096;                          // EW*16*XPITCH
    int*   m_row = (int*)(xs + EW * 16 * XPITCH);
    int*   m_on  = m_row + EW * 16;
    float* m_sc  = (float*)(m_on + EW * 16);

    int b = blockIdx.x - LIN_BLOCKS;
    int dir = b & 1;
    int t = (b >> 1) & 31;
    int chunk = b >> 6;                               // 0..EC-1

    const float4* Wg = (const float4*)(((dir == 0) ? wf : wb) + (size_t)t * 4096);
    float4* Wsw = (float4*)Ws;
    for (int j = threadIdx.x; j < 1024; j += 128) Wsw[j] = Wg[j];
    __syncthreads();

    int start = g_off[t], end = g_off[t + 1];
    float wsc = g_wscale[dir * NUM_RELS + t];

    int wid  = threadIdx.x >> 5;
    int lane = threadIdx.x & 31;
    int tg = lane & 3;
    int og = lane >> 2;
    float* xw = xs + wid * 16 * XPITCH;
    int*   rw  = m_row + wid * 16;
    int*   onw = m_on + wid * 16;
    float* scw = m_sc + wid * 16;

    int half = lane >> 4;
    int c    = lane & 15;

    for (int base = start + (chunk * EW + wid) * 16; base < end;
         base += EC * EW * 16) {
        int nE = min(16, end - base);

        if (lane < 16) {
            int row = 0, onode = 0;
            float sc = 0.f;
            if (lane < nE) {
                int es = g_esrc[base + lane];
                int ed = g_edst[base + lane];
                row   = dir ? ed : es;
                onode = dir ? es : ed;
                int deg = dir ? G_DEG_DST[row] : G_DEG_SRC[row];
                sc = wsc * __fdividef(1.0f, (float)(deg + 1));
            }
            rw[lane] = row;
            onw[lane] = onode;
            scw[lane] = sc;
        }
        __syncwarp();

        #pragma unroll
        for (int it = 0; it < 8; it++) {
            int r = it * 2 + half;
            int rg = rw[r];
            float4 v = *(const float4*)(x + (size_t)rg * 64 + c * 4);
            *(float4*)(xw + r * XPITCH + c * 4) = v;
        }
        __syncwarp();

        unsigned long long acc[4][4];
        #pragma unroll
        for (int j = 0; j < 4; j++)
            #pragma unroll
            for (int p = 0; p < 4; p++) acc[j][p] = 0ull;

        // prefetched, fully unrolled K loop
        float4 xv[4];
        #pragma unroll
        for (int j = 0; j < 4; j++)
            xv[j] = *(const float4*)(xw + (4 * j + tg) * XPITCH);

        #pragma unroll
        for (int c4 = 0; c4 < 16; c4++) {
            float4 xn[4];
            if (c4 < 15) {
                #pragma unroll
                for (int j = 0; j < 4; j++)
                    xn[j] = *(const float4*)(xw + (4 * j + tg) * XPITCH + (c4 + 1) * 4);
            }
            #pragma unroll
            for (int r = 0; r < 4; r++) {
                const double2* wp = (const double2*)(Ws + (c4 * 4 + r) * 64 + og * 8);
                double2 w0 = wp[0], w1 = wp[1];
                unsigned long long b0 = d_as_ull(w0.x), b1 = d_as_ull(w0.y);
                unsigned long long b2 = d_as_ull(w1.x), b3 = d_as_ull(w1.y);
                #pragma unroll
                for (int j = 0; j < 4; j++) {
                    float xi = (r == 0) ? xv[j].x : (r == 1) ? xv[j].y
                             : (r == 2) ? xv[j].z : xv[j].w;
                    unsigned long long xi2 = pack2(xi);
                    fma2(acc[j][0], xi2, b0);
                    fma2(acc[j][1], xi2, b1);
                    fma2(acc[j][2], xi2, b2);
                    fma2(acc[j][3], xi2, b3);
                }
            }
            #pragma unroll
            for (int j = 0; j < 4; j++) xv[j] = xn[j];
        }

        #pragma unroll
        for (int j = 0; j < 4; j++) {
            int e = 4 * j + tg;
            if (e < nE) {
                float s = scw[e];
                int on = onw[e];
                float a0, a1, a2, a3, a4, a5, a6, a7;
                unpack2(acc[j][0], a0, a1);
                unpack2(acc[j][1], a2, a3);
                unpack2(acc[j][2], a4, a5);
                unpack2(acc[j][3], a6, a7);
                float* op = out + (size_t)on * 64 + og * 8;
                asm volatile("red.global.add.v4.f32 [%0], {%1, %2, %3, %4};"
                             :: "l"(op), "f"(a0 * s), "f"(a1 * s),
                                "f"(a2 * s), "f"(a3 * s) : "memory");
                asm volatile("red.global.add.v4.f32 [%0], {%1, %2, %3, %4};"
                             :: "l"(op + 4), "f"(a4 * s), "f"(a5 * s),
                                "f"(a6 * s), "f"(a7 * s) : "memory");
            }
        }
        __syncwarp();
    }
}

#define EDGE_SMEM ((4096 + EW * 16 * XPITCH) * 4 + EW * 16 * 12)

// ---------------- launch ----------------------------------------------------
extern "C" void kernel_launch(void* const* d_in, const int* in_sizes, int n_in,
                              void* d_out, int out_size) {
    const float* x   = (const float*)d_in[0];
    const int*   ei  = (const int*)d_in[1];     // [2, E] int32
    const int*   et  = (const int*)d_in[2];     // [E]    int32
    const float* wf  = (const float*)d_in[3];
    const float* wb  = (const float*)d_in[4];
    const float* lw  = (const float*)d_in[5];
    const float* lb  = (const float*)d_in[6];
    float*       out = (float*)d_out;

    (void)in_sizes; (void)n_in; (void)out_size;

    void* prepAddr = nullptr;
    cudaGetSymbolAddress(&prepAddr, g_prep);
    cudaFuncSetAttribute(k_edge, cudaFuncAttributeMaxDynamicSharedMemorySize,
                         EDGE_SMEM);

    cudaMemsetAsync(prepAddr, 0, sizeof(int) * PREP_INTS, 0);
    cudaMemsetAsync(out, 0, sizeof(float) * N_NODES * OUT_C, 0);
    k_count<<<EDGE_BLOCKS + WSCALE_BLOCKS, 256>>>(ei, et, wf, wb);
    k_scatter<<<EDGE_BLOCKS, 256>>>(ei, et);
    k_edge<<<LIN_BLOCKS + 2 * NUM_RELS * EC, 128, EDGE_SMEM>>>(x, wf, wb, lw, lb, out);
}

// round 10
// speedup vs baseline: 3.4159x; 1.3735x over previous
#include <cuda_runtime.h>
#include <math.h>

#define IN_C   64
#define OUT_C  64
#define NUM_RELS 32
#define N_NODES 20000
#define N_EDGES 50000
#define EDGE_BLOCKS ((N_EDGES + 255) / 256)       // 196
#define WSCALE_BLOCKS (2 * NUM_RELS)              // 64
#define EC 13
#define EW 4
#define XPITCH 68
#define LIN_BLOCKS ((N_NODES + 127) / 128)        // 157

// ---------------- device scratch ----------------
#define PREP_INTS (2 * N_NODES + 2 * NUM_RELS + 1)
__device__ __align__(16) int g_prep[PREP_INTS];
#define G_DEG_SRC  (g_prep)
#define G_DEG_DST  (g_prep + N_NODES)
#define G_HIST     (g_prep + 2 * N_NODES)
#define G_CURSOR   (g_prep + 2 * N_NODES + NUM_RELS)
#define G_TICKET   (g_prep + 2 * N_NODES + 2 * NUM_RELS)

__device__ int   g_off[NUM_RELS + 1];
__device__ float g_wscale[2 * NUM_RELS];
__device__ int   g_esrc[N_EDGES];
__device__ int   g_edst[N_EDGES];

// ---- packed f32x2 helpers ----
__device__ __forceinline__ void fma2(unsigned long long& d,
                                     unsigned long long a, unsigned long long b) {
    asm("fma.rn.f32x2 %0, %1, %2, %0;" : "+l"(d) : "l"(a), "l"(b));
}
__device__ __forceinline__ unsigned long long pack2(float v) {
    unsigned long long r;
    asm("mov.b64 %0, {%1, %1};" : "=l"(r) : "f"(v));
    return r;
}
__device__ __forceinline__ void unpack2(unsigned long long v, float& lo, float& hi) {
    asm("mov.b64 {%0, %1}, %2;" : "=f"(lo), "=f"(hi) : "l"(v));
}
__device__ __forceinline__ unsigned long long d_as_ull(double d) {
    return __double_as_longlong(d);
}

// ---------------- k_count: type histogram + tail-block scan ONLY -------------
__global__ void __launch_bounds__(256) k_count(const int* __restrict__ et) {
    __shared__ int sh[NUM_RELS];
    __shared__ int isLast;
    if (threadIdx.x < NUM_RELS) sh[threadIdx.x] = 0;
    __syncthreads();
    int e = blockIdx.x * 256 + threadIdx.x;
    if (e < N_EDGES) atomicAdd(&sh[et[e]], 1);
    __syncthreads();
    if (threadIdx.x < NUM_RELS && sh[threadIdx.x])
        atomicAdd(&G_HIST[threadIdx.x], sh[threadIdx.x]);
    __threadfence();
    if (threadIdx.x == 0)
        isLast = (atomicAdd(G_TICKET, 1) == EDGE_BLOCKS - 1);
    __syncthreads();
    if (isLast && threadIdx.x < 32) {
        int t = threadIdx.x;
        int s = atomicAdd(&G_HIST[t], 0);
        #pragma unroll
        for (int d = 1; d < 32; d <<= 1) {
            int n = __shfl_up_sync(0xffffffffu, s, d);
            if (t >= d) s += n;
        }
        g_off[t + 1] = s;
        if (t == 0) g_off[0] = 0;
    }
}

// ---------------- k_scatter: degrees + counting-sort scatter | wscale --------
__global__ void __launch_bounds__(256) k_scatter(const int* __restrict__ ei,
                                                 const int* __restrict__ et,
                                                 const float* __restrict__ wf,
                                                 const float* __restrict__ wb) {
    int b = blockIdx.x;
    if (b < EDGE_BLOCKS) {
        __shared__ int lh[NUM_RELS];
        __shared__ int lbase[NUM_RELS];
        if (threadIdx.x < NUM_RELS) lh[threadIdx.x] = 0;
        __syncthreads();
        int e = b * 256 + threadIdx.x;
        int s = 0, d = 0, t = -1, myrank = 0;
        if (e < N_EDGES) {
            s = ei[e];
            d = ei[N_EDGES + e];
            t = et[e];
            atomicAdd(&G_DEG_SRC[s], 1);
            atomicAdd(&G_DEG_DST[d], 1);
            myrank = atomicAdd(&lh[t], 1);
        }
        __syncthreads();
        if (threadIdx.x < NUM_RELS) {
            int c = lh[threadIdx.x];
            lbase[threadIdx.x] = c ? atomicAdd(&G_CURSOR[threadIdx.x], c) : 0;
        }
        __syncthreads();
        if (e < N_EDGES) {
            int p = g_off[t] + lbase[t] + myrank;
            g_esrc[p] = s;
            g_edst[p] = d;
        }
    } else {
        int m = b - EDGE_BLOCKS;   // 0..63
        const float4* src = (const float4*)((m < NUM_RELS)
                            ? (wf + (size_t)m * 4096)
                            : (wb + (size_t)(m - NUM_RELS) * 4096));
        __shared__ float red[8];
        float sq = 0.f;
        #pragma unroll
        for (int j = 0; j < 4; j++) {
            float4 v = src[threadIdx.x + j * 256];
            sq += v.x * v.x + v.y * v.y + v.z * v.z + v.w * v.w;
        }
        #pragma unroll
        for (int dd = 16; dd > 0; dd >>= 1) sq += __shfl_xor_sync(0xffffffffu, sq, dd);
        if ((threadIdx.x & 31) == 0) red[threadIdx.x >> 5] = sq;
        __syncthreads();
        if (threadIdx.x == 0) {
            float tot = 0.f;
            #pragma unroll
            for (int w = 0; w < 8; w++) tot += red[w];
            g_wscale[m] = 1.0f / (sqrtf(tot) + 0.01f);
        }
    }
}

// ---------------- k_linear: side-stream dense term (red.add into zeroed out) -
__global__ void __launch_bounds__(128) k_linear(const float* __restrict__ x,
                                                const float* __restrict__ lw,
                                                const float* __restrict__ lb,
                                                float* __restrict__ out) {
    __shared__ __align__(16) float Ls[64 * 64];   // Ls[i*64+o] = lw[o*64+i]
    __shared__ float Bs[64];
    for (int j = threadIdx.x; j < 4096; j += 128) {
        int o = j >> 6, i = j & 63;
        Ls[i * 64 + o] = lw[j];
    }
    if (threadIdx.x < 64) Bs[threadIdx.x] = lb[threadIdx.x];
    __syncthreads();

    int n = blockIdx.x * 128 + threadIdx.x;
    if (n >= N_NODES) return;

    unsigned long long acc[32];
    #pragma unroll
    for (int k = 0; k < 32; k++) acc[k] = 0ull;

    const float4* xr = (const float4*)(x + (size_t)n * 64);
    #pragma unroll 1
    for (int i4 = 0; i4 < 16; i4++) {
        float4 v = xr[i4];
        float vs[4] = {v.x, v.y, v.z, v.w};
        #pragma unroll
        for (int j = 0; j < 4; j++) {
            unsigned long long vv = pack2(vs[j]);
            const double2* wrow = (const double2*)(Ls + ((i4 * 4 + j) << 6));
            #pragma unroll
            for (int o4 = 0; o4 < 16; o4++) {
                double2 w = wrow[o4];
                fma2(acc[2 * o4], vv, d_as_ull(w.x));
                fma2(acc[2 * o4 + 1], vv, d_as_ull(w.y));
            }
        }
    }
    float* op = out + (size_t)n * 64;
    const float4* B4 = (const float4*)Bs;
    #pragma unroll
    for (int o = 0; o < 16; o++) {
        float a0, a1, a2, a3;
        unpack2(acc[2 * o], a0, a1);
        unpack2(acc[2 * o + 1], a2, a3);
        float4 bb = B4[o];
        asm volatile("red.global.add.v4.f32 [%0], {%1, %2, %3, %4};"
                     :: "l"(op + o * 4), "f"(a0 + bb.x), "f"(a1 + bb.y),
                        "f"(a2 + bb.z), "f"(a3 + bb.w) : "memory");
    }
}

// ---------------- k_edge: 4 edges x 8 outs per thread, 16-edge warp tiles ----
__global__ void __launch_bounds__(128, 6) k_edge(const float* __restrict__ x,
                                                 const float* __restrict__ wf,
                                                 const float* __restrict__ wb,
                                                 float* __restrict__ out) {
    extern __shared__ __align__(16) float smem[];
    float* Ws = smem;                                 // 4096 floats
    float* xs = smem + 4096;                          // EW*16*XPITCH
    int*   m_row = (int*)(xs + EW * 16 * XPITCH);
    int*   m_on  = m_row + EW * 16;
    float* m_sc  = (float*)(m_on + EW * 16);

    int b = blockIdx.x;
    int dir = b & 1;
    int t = (b >> 1) & 31;
    int chunk = b >> 6;                               // 0..EC-1

    const float4* Wg = (const float4*)(((dir == 0) ? wf : wb) + (size_t)t * 4096);
    float4* Wsw = (float4*)Ws;
    for (int j = threadIdx.x; j < 1024; j += 128) Wsw[j] = Wg[j];
    __syncthreads();

    int start = g_off[t], end = g_off[t + 1];
    float wsc = g_wscale[dir * NUM_RELS + t];

    int wid  = threadIdx.x >> 5;
    int lane = threadIdx.x & 31;
    int tg = lane & 3;
    int og = lane >> 2;
    float* xw = xs + wid * 16 * XPITCH;
    int*   rw  = m_row + wid * 16;
    int*   onw = m_on + wid * 16;
    float* scw = m_sc + wid * 16;

    int half = lane >> 4;
    int c    = lane & 15;

    for (int base = start + (chunk * EW + wid) * 16; base < end;
         base += EC * EW * 16) {
        int nE = min(16, end - base);

        if (lane < 16) {
            int row = 0, onode = 0;
            float sc = 0.f;
            if (lane < nE) {
                int es = g_esrc[base + lane];
                int ed = g_edst[base + lane];
                row   = dir ? ed : es;
                onode = dir ? es : ed;
                int deg = dir ? G_DEG_DST[row] : G_DEG_SRC[row];
                sc = wsc * __fdividef(1.0f, (float)(deg + 1));
            }
            rw[lane] = row;
            onw[lane] = onode;
            scw[lane] = sc;
        }
        __syncwarp();

        #pragma unroll
        for (int it = 0; it < 8; it++) {
            int r = it * 2 + half;
            int rg = rw[r];
            float4 v = *(const float4*)(x + (size_t)rg * 64 + c * 4);
            *(float4*)(xw + r * XPITCH + c * 4) = v;
        }
        __syncwarp();

        unsigned long long acc[4][4];
        #pragma unroll
        for (int j = 0; j < 4; j++)
            #pragma unroll
            for (int p = 0; p < 4; p++) acc[j][p] = 0ull;

        float4 xv[4];
        #pragma unroll
        for (int j = 0; j < 4; j++)
            xv[j] = *(const float4*)(xw + (4 * j + tg) * XPITCH);

        #pragma unroll
        for (int c4 = 0; c4 < 16; c4++) {
            float4 xn[4];
            if (c4 < 15) {
                #pragma unroll
                for (int j = 0; j < 4; j++)
                    xn[j] = *(const float4*)(xw + (4 * j + tg) * XPITCH + (c4 + 1) * 4);
            }
            #pragma unroll
            for (int r = 0; r < 4; r++) {
                const double2* wp = (const double2*)(Ws + (c4 * 4 + r) * 64 + og * 8);
                double2 w0 = wp[0], w1 = wp[1];
                unsigned long long b0 = d_as_ull(w0.x), b1 = d_as_ull(w0.y);
                unsigned long long b2 = d_as_ull(w1.x), b3 = d_as_ull(w1.y);
                #pragma unroll
                for (int j = 0; j < 4; j++) {
                    float xi = (r == 0) ? xv[j].x : (r == 1) ? xv[j].y
                             : (r == 2) ? xv[j].z : xv[j].w;
                    unsigned long long xi2 = pack2(xi);
                    fma2(acc[j][0], xi2, b0);
                    fma2(acc[j][1], xi2, b1);
                    fma2(acc[j][2], xi2, b2);
                    fma2(acc[j][3], xi2, b3);
                }
            }
            #pragma unroll
            for (int j = 0; j < 4; j++) xv[j] = xn[j];
        }

        #pragma unroll
        for (int j = 0; j < 4; j++) {
            int e = 4 * j + tg;
            if (e < nE) {
                float s = scw[e];
                int on = onw[e];
                float a0, a1, a2, a3, a4, a5, a6, a7;
                unpack2(acc[j][0], a0, a1);
                unpack2(acc[j][1], a2, a3);
                unpack2(acc[j][2], a4, a5);
                unpack2(acc[j][3], a6, a7);
                float* op = out + (size_t)on * 64 + og * 8;
                asm volatile("red.global.add.v4.f32 [%0], {%1, %2, %3, %4};"
                             :: "l"(op), "f"(a0 * s), "f"(a1 * s),
                                "f"(a2 * s), "f"(a3 * s) : "memory");
                asm volatile("red.global.add.v4.f32 [%0], {%1, %2, %3, %4};"
                             :: "l"(op + 4), "f"(a4 * s), "f"(a5 * s),
                                "f"(a6 * s), "f"(a7 * s) : "memory");
            }
        }
        __syncwarp();
    }
}

#define EDGE_SMEM ((4096 + EW * 16 * XPITCH) * 4 + EW * 16 * 12)

// ---------------- launch: fork/join with side-stream linear ------------------
extern "C" void kernel_launch(void* const* d_in, const int* in_sizes, int n_in,
                              void* d_out, int out_size) {
    const float* x   = (const float*)d_in[0];
    const int*   ei  = (const int*)d_in[1];     // [2, E] int32
    const int*   et  = (const int*)d_in[2];     // [E]    int32
    const float* wf  = (const float*)d_in[3];
    const float* wb  = (const float*)d_in[4];
    const float* lw  = (const float*)d_in[5];
    const float* lb  = (const float*)d_in[6];
    float*       out = (float*)d_out;

    (void)in_sizes; (void)n_in; (void)out_size;

    void* prepAddr = nullptr;
    cudaGetSymbolAddress(&prepAddr, g_prep);
    cudaFuncSetAttribute(k_edge, cudaFuncAttributeMaxDynamicSharedMemorySize,
                         EDGE_SMEM);

    cudaStream_t sB;
    cudaEvent_t evRoot, evZ, evB;
    cudaStreamCreateWithFlags(&sB, cudaStreamNonBlocking);
    cudaEventCreateWithFlags(&evRoot, cudaEventDisableTiming);
    cudaEventCreateWithFlags(&evZ, cudaEventDisableTiming);
    cudaEventCreateWithFlags(&evB, cudaEventDisableTiming);

    // fork side stream
    cudaEventRecord(evRoot, 0);
    cudaStreamWaitEvent(sB, evRoot, 0);

    // side: zero out -> dense linear (red.add)
    cudaMemsetAsync(out, 0, sizeof(float) * N_NODES * OUT_C, sB);
    cudaEventRecord(evZ, sB);                 // out is zeroed
    k_linear<<<LIN_BLOCKS, 128, 0, sB>>>(x, lw, lb, out);
    cudaEventRecord(evB, sB);                 // linear done

    // main: zero prep -> hist+scan -> degrees+scatter+wscale
    cudaMemsetAsync(prepAddr, 0, sizeof(int) * PREP_INTS, 0);
    k_count<<<EDGE_BLOCKS, 256>>>(et);
    k_scatter<<<EDGE_BLOCKS + WSCALE_BLOCKS, 256>>>(ei, et, wf, wb);

    // edge kernel needs out zeroed (linear may still be running — both red.add)
    cudaStreamWaitEvent(0, evZ, 0);
    k_edge<<<2 * NUM_RELS * EC, 128, EDGE_SMEM>>>(x, wf, wb, out);

    // join: result complete only after linear too
    cudaStreamWaitEvent(0, evB, 0);

    cudaEventDestroy(evRoot);
    cudaEventDestroy(evZ);
    cudaEventDestroy(evB);
    cudaStreamDestroy(sB);
}